// round 10
// baseline (speedup 1.0000x reference)
#include <cuda_runtime.h>

// SIREN fused inference for sm_103a.
// N=1e6 points, D=3, F=128, L=8 residual blocks, O=1.
// Fully fused: activations live in SMEM per 128-point CTA tile; weights are
// restaged from L2 per sublayer into a row-PADDED smem tile (stride 130
// floats -> the warp's two feature groups land 16 banks apart, N=1).
// Compute path is packed fp32 FMA (fma.rn.f32x2), 2 points per 64-bit reg:
// 2x the FFMA issue rate -> fma-pipe-bound at ~72 TF/s effective fp32.
//
// Cycle model (per SMSP, 2 warps): 64 FMA2 x rt2 = 128 cyc/k (binding);
// crossbar 96 phases/SM/k; staging ~1K cyc/sublayer (6% overhead, serial by
// design -- double-buffered weights don't fit beside the 128KB Hs/Ss).

#define OMEGA_F 30.0f
constexpr int F       = 128;   // feature width
constexpr int FP      = 130;   // padded weight row stride (floats): breaks the
                               // 4096B == 0 (mod 128) same-bank collision
constexpr int TILE    = 128;   // points per CTA
constexpr int PAIRS   = 64;    // point pairs per CTA
constexpr int NT      = 256;   // threads per CTA
constexpr int NLAYERS = 8;

// Packed fp32x2 FMA (sm_100+). d = a*b + c elementwise on two packed f32.
#define FMA2(d, a, b, c) \
    asm("fma.rn.f32x2 %0, %1, %2, %3;" : "=l"(d) : "l"(a), "l"(b), "l"(c))

__device__ __forceinline__ unsigned long long dup32(float w) {
    unsigned u = __float_as_uint(w);
    unsigned long long d;
    asm("mov.b64 %0, {%1, %1};" : "=l"(d) : "r"(u));
    return d;
}

__device__ __forceinline__ float2 unpack64(unsigned long long v) {
    float2 r;
    asm("mov.b64 {%0, %1}, %2;" : "=f"(r.x), "=f"(r.y) : "l"(v));
    return r;
}

// One GEMM + sin sublayer over the CTA tile.
//   Dst[f][pair] = sin( scale * sum_k W[f][k]*Src[k][pair] + bs[f] )
// bs[] is pre-multiplied by OMEGA. If RES: Dst = w_out * (Dst + sin(...)).
// Thread tile: 4 pairs (PT + 16*j) x 8 features (FTb + i).
template <bool RES>
__device__ __forceinline__ void gemm_act(
    const unsigned long long* __restrict__ Src,  // [F][PAIRS] packed float2
    float2* __restrict__ Dst,                    // [F][PAIRS]
    const float* __restrict__ Ws,                // [F][FP] padded row-major
    const float* __restrict__ bs,                // [F], already * OMEGA
    float scale, float w_out, int PT, int FTb)
{
    unsigned long long acc[4][8];
#pragma unroll
    for (int j = 0; j < 4; j++)
#pragma unroll
        for (int i = 0; i < 8; i++) acc[j][i] = 0ULL;

#pragma unroll 4
    for (int k = 0; k < F; k++) {
        unsigned long long hv[4];
#pragma unroll
        for (int j = 0; j < 4; j++)
            hv[j] = Src[k * PAIRS + PT + 16 * j];   // 128B contig: N=1 LDS.64
#pragma unroll
        for (int i = 0; i < 8; i++) {
            // two FTb groups/warp -> addrs differ by 8*FP*4=4160B -> bank+16
            unsigned long long wd = dup32(Ws[(FTb + i) * FP + k]);
#pragma unroll
            for (int j = 0; j < 4; j++) FMA2(acc[j][i], hv[j], wd, acc[j][i]);
        }
    }

#pragma unroll
    for (int i = 0; i < 8; i++) {
        float ob = bs[FTb + i];
#pragma unroll
        for (int j = 0; j < 4; j++) {
            float2 a = unpack64(acc[j][i]);
            float s0 = __sinf(fmaf(a.x, scale, ob));
            float s1 = __sinf(fmaf(a.y, scale, ob));
            int idx = (FTb + i) * PAIRS + PT + 16 * j;
            if (RES) {
                float2 h = Dst[idx];
                s0 = w_out * (h.x + s0);
                s1 = w_out * (h.y + s1);
            }
            Dst[idx] = make_float2(s0, s1);
        }
    }
}

__global__ void __launch_bounds__(NT, 1) siren_fused_kernel(
    const float* __restrict__ coords,
    const float* __restrict__ W_first, const float* __restrict__ b_first,
    const float* __restrict__ W1, const float* __restrict__ b1,
    const float* __restrict__ W2, const float* __restrict__ b2,
    const float* __restrict__ W_out, const float* __restrict__ b_out,
    float* __restrict__ out, int N)
{
    extern __shared__ float smem[];
    float2* Hs = (float2*)smem;              // [F][PAIRS] running activation h
    float2* Ss = Hs + F * PAIRS;             // [F][PAIRS] intermediate s1
    float*  Ws = (float*)(Ss + F * PAIRS);   // [F][FP] padded weight tile
    float*  bs = Ws + F * FP;                // [F] bias (pre-scaled by OMEGA)
    float*  cs = bs + F;                     // [TILE*3] staged coords

    const int tid  = threadIdx.x;
    const int PT   = tid & 15;        // pairs PT, PT+16, PT+32, PT+48
    const int FTb  = (tid >> 4) * 8;  // feature tile base
    const int base = blockIdx.x * TILE;

    // Stage coords (zero-pad past N).
    for (int idx = tid; idx < TILE * 3; idx += NT) {
        int g = base * 3 + idx;
        cs[idx] = (g < N * 3) ? coords[g] : 0.0f;
    }
    // Stage first-layer weights (unpadded [F][3] layout in Ws).
    for (int idx = tid; idx < F * 3; idx += NT) Ws[idx] = W_first[idx];
    if (tid < F) bs[tid] = b_first[tid];
    __syncthreads();

    // First SIREN layer: h = sin(OMEGA * (W_first x + b_first)).
    // Args reach ~+-47 here -> accurate sinf (only F per point, cheap).
#pragma unroll
    for (int i = 0; i < 8; i++) {
        int f = FTb + i;
        float w0 = Ws[f * 3 + 0], w1 = Ws[f * 3 + 1], w2 = Ws[f * 3 + 2];
        float bb = bs[f];
#pragma unroll
        for (int j = 0; j < 4; j++) {
            int pair = PT + 16 * j;
            int m0 = 2 * pair, m1 = 2 * pair + 1;
            float a0 = fmaf(w0, cs[m0 * 3], fmaf(w1, cs[m0 * 3 + 1], fmaf(w2, cs[m0 * 3 + 2], bb)));
            float a1 = fmaf(w0, cs[m1 * 3], fmaf(w1, cs[m1 * 3 + 1], fmaf(w2, cs[m1 * 3 + 2], bb)));
            Hs[f * PAIRS + pair] = make_float2(sinf(OMEGA_F * a0), sinf(OMEGA_F * a1));
        }
    }

    // Residual blocks.
    for (int l = 0; l < NLAYERS; l++) {
        // sin(OMEGA*((w_in*h)@W1^T + b1)) == sin((OMEGA*w_in)*(h@W1^T) + OMEGA*b1)
        float sc1   = (l > 0) ? (OMEGA_F * 0.5f) : OMEGA_F;
        float w_out = (l == NLAYERS - 1) ? 0.5f : 1.0f;

        __syncthreads();  // previous consumers of Ws / Hs done
        {   // stage W1[l] into padded tile: float2 rows of 65 (=130 floats)
            const float2* src = (const float2*)(W1 + l * F * F);
            float2* dst = (float2*)Ws;
            for (int idx = tid; idx < F * F / 2; idx += NT) {
                int r = idx >> 6, c = idx & 63;
                dst[r * (FP / 2) + c] = src[idx];
            }
        }
        if (tid < F) bs[tid] = OMEGA_F * b1[l * F + tid];
        __syncthreads();
        gemm_act<false>((const unsigned long long*)Hs, Ss, Ws, bs, sc1, 1.0f, PT, FTb);

        __syncthreads();  // GEMM1 (reads Ws, writes Ss) done
        {
            const float2* src = (const float2*)(W2 + l * F * F);
            float2* dst = (float2*)Ws;
            for (int idx = tid; idx < F * F / 2; idx += NT) {
                int r = idx >> 6, c = idx & 63;
                dst[r * (FP / 2) + c] = src[idx];
            }
        }
        if (tid < F) bs[tid] = OMEGA_F * b2[l * F + tid];
        __syncthreads();
        // h = w_out * (h + sin(OMEGA*(s1@W2^T + b2))); each (f,pair) cell of Hs
        // is read+written only by its owning thread -> no race.
        gemm_act<true>((const unsigned long long*)Ss, Hs, Ws, bs, OMEGA_F, w_out, PT, FTb);
    }

    // Output head: out[m] = h[m] . W_out + b_out  (O == 1).
    __syncthreads();   // make all Hs writes visible; Ws consumers done
    if (tid < F) Ws[tid] = W_out[tid];
    __syncthreads();
    if (tid < TILE) {
        int p = base + tid;
        if (p < N) {
            int pair = tid >> 1;
            int half = tid & 1;
            float sum = 0.0f;
#pragma unroll 8
            for (int f = 0; f < F; f++) {
                float2 v = Hs[f * PAIRS + pair];
                sum = fmaf(half ? v.y : v.x, Ws[f], sum);
            }
            out[p] = sum + b_out[0];
        }
    }
}

extern "C" void kernel_launch(void* const* d_in, const int* in_sizes, int n_in,
                              void* d_out, int out_size)
{
    const float* coords  = (const float*)d_in[0];
    const float* W_first = (const float*)d_in[1];
    const float* b_first = (const float*)d_in[2];
    const float* W1      = (const float*)d_in[3];
    const float* b1      = (const float*)d_in[4];
    const float* W2      = (const float*)d_in[5];
    const float* b2      = (const float*)d_in[6];
    const float* W_out   = (const float*)d_in[7];
    const float* b_out   = (const float*)d_in[8];
    float* out = (float*)d_out;

    int N = in_sizes[0] / 3;
    int blocks = (N + TILE - 1) / TILE;

    // Hs + Ss + padded Ws + bs + cs
    size_t smem_bytes = (size_t)(2 * F * PAIRS * 2 + F * FP + F + TILE * 3) * sizeof(float);

    cudaFuncSetAttribute(siren_fused_kernel,
                         cudaFuncAttributeMaxDynamicSharedMemorySize,
                         (int)smem_bytes);

    siren_fused_kernel<<<blocks, NT, smem_bytes>>>(
        coords, W_first, b_first, W1, b1, W2, b2, W_out, b_out, out, N);
}